// round 1
// baseline (speedup 1.0000x reference)
#include <cuda_runtime.h>

// Problem constants
#define NB   128
#define CCH  3
#define HH   128
#define WW   128
#define LL   4096
#define D1   1204
#define D2   4816
#define MROWS (NB*CCH)          // 384
#define SPLITK 4
#define KCHUNK (LL/SPLITK)      // 1024

// GEMM tile config
#define BM 64
#define BN 64
#define BK 16
#define PADW 68                 // BM + 4 pad (keeps 16B alignment, halves STS conflicts)

// ---------------- device scratch (no allocations allowed) ----------------
__device__ __align__(16) float g_s [MROWS*LL];          // masked gather   6.3 MB
__device__ __align__(16) float g_hp[SPLITK*MROWS*D1];   // splitK partials 7.4 MB
__device__ __align__(16) float g_h1[MROWS*D1];          // leaky(h1)       1.85 MB
__device__ __align__(16) float g_h2[MROWS*D2];          // leaky(h2)       7.4 MB
__device__ float g_aff1[6];                             // a0,a1,a2,b0,b1,b2
__device__ float g_aff2[6];
__device__ float g_part[3*16*2];                        // stats partials

// ---------------- gather + mask ----------------
__global__ void gather_kernel(const float* __restrict__ x,
                              const int*   __restrict__ coords,
                              const float* __restrict__ mask)
{
    int idx = blockIdx.x * blockDim.x + threadIdx.x;
    if (idx >= MROWS * LL) return;
    int l = idx & (LL - 1);
    int m = idx >> 12;              // idx / 4096
    int n = m / 3;
    int off = coords[2*l] * WW + coords[2*l + 1];
    float v = x[(size_t)m * (HH*WW) + off];
    if (mask[(size_t)n * LL + l] < 0.3f) v = 0.0f;
    g_s[idx] = v;
}

// ---------------- generic C = A * B^T tile GEMM ----------------
// A: [M, K] row-major (lda), B: [Brows, K] row-major (ldb). 256 threads, 64x64 tile.
// Optional per-row affine on A (BN fold), per-col bias + leaky on output.
// blockIdx.z = split-K slice; output offset by z*zStride.
__global__ __launch_bounds__(256)
void gemm_tn(const float* __restrict__ A, int lda,
             const float* __restrict__ B, int ldb, int Brows,
             float* __restrict__ C, int N,
             int Ktot, int kChunk, size_t zStride,
             const float* __restrict__ rowAffine,
             const float* __restrict__ colBias,
             int applyLeaky)
{
    __shared__ __align__(16) float As[BK][PADW];
    __shared__ __align__(16) float Bs[BK][PADW];

    int tid = threadIdx.x;
    int tx = tid & 15;              // 0..15 (N dir)
    int ty = tid >> 4;              // 0..15 (M dir)
    int m0 = blockIdx.y * BM;
    int n0 = blockIdx.x * BN;
    int kBegin = blockIdx.z * kChunk;
    int kEnd   = min(kBegin + kChunk, Ktot);
    C += (size_t)blockIdx.z * zStride;

    int ldRow = tid >> 2;           // 0..63
    int ldK   = (tid & 3) * 4;      // 0,4,8,12

    float aScale = 1.0f, aShift = 0.0f;
    if (rowAffine) {
        int c = (m0 + ldRow) % 3;
        aScale = rowAffine[c];
        aShift = rowAffine[3 + c];
    }

    const float* Ap = A + (size_t)(m0 + ldRow) * lda;
    int bRow = n0 + ldRow;
    const float* Bp = B + (size_t)bRow * ldb;
    bool bOK = bRow < Brows;

    float acc[4][4];
    #pragma unroll
    for (int i = 0; i < 4; i++)
        #pragma unroll
        for (int j = 0; j < 4; j++) acc[i][j] = 0.0f;

    for (int kt = kBegin; kt < kEnd; kt += BK) {
        int k = kt + ldK;
        // A tile (rows always valid: M=384 multiple of 64)
        if (k + 3 < kEnd) {
            float4 v = *reinterpret_cast<const float4*>(Ap + k);
            As[ldK+0][ldRow] = v.x * aScale + aShift;
            As[ldK+1][ldRow] = v.y * aScale + aShift;
            As[ldK+2][ldRow] = v.z * aScale + aShift;
            As[ldK+3][ldRow] = v.w * aScale + aShift;
        } else {
            #pragma unroll
            for (int i = 0; i < 4; i++)
                As[ldK+i][ldRow] = (k + i < kEnd) ? Ap[k+i] * aScale + aShift : 0.0f;
        }
        // B tile (row-guarded)
        if (bOK && (k + 3 < kEnd)) {
            float4 v = *reinterpret_cast<const float4*>(Bp + k);
            Bs[ldK+0][ldRow] = v.x;
            Bs[ldK+1][ldRow] = v.y;
            Bs[ldK+2][ldRow] = v.z;
            Bs[ldK+3][ldRow] = v.w;
        } else {
            #pragma unroll
            for (int i = 0; i < 4; i++)
                Bs[ldK+i][ldRow] = (bOK && (k + i < kEnd)) ? Bp[k+i] : 0.0f;
        }
        __syncthreads();

        #pragma unroll
        for (int kk = 0; kk < BK; kk++) {
            float4 av = *reinterpret_cast<const float4*>(&As[kk][ty * 4]);
            float4 bv = *reinterpret_cast<const float4*>(&Bs[kk][tx * 4]);
            float a[4] = {av.x, av.y, av.z, av.w};
            float b[4] = {bv.x, bv.y, bv.z, bv.w};
            #pragma unroll
            for (int i = 0; i < 4; i++)
                #pragma unroll
                for (int j = 0; j < 4; j++)
                    acc[i][j] += a[i] * b[j];
        }
        __syncthreads();
    }

    #pragma unroll
    for (int i = 0; i < 4; i++) {
        int m = m0 + ty * 4 + i;
        #pragma unroll
        for (int j = 0; j < 4; j++) {
            int n = n0 + tx * 4 + j;
            if (n < N) {
                float v = acc[i][j];
                if (colBias) v += colBias[n];
                if (applyLeaky) v = (v >= 0.0f) ? v : 0.01f * v;
                C[(size_t)m * N + n] = v;
            }
        }
    }
}

// ---------------- splitK combine + bias + leaky -> h1 ----------------
__global__ void combine_kernel(const float* __restrict__ b1)
{
    int idx = blockIdx.x * blockDim.x + threadIdx.x;
    if (idx >= MROWS * D1) return;
    const int MN = MROWS * D1;
    float v = g_hp[idx] + g_hp[MN + idx] + g_hp[2*MN + idx] + g_hp[3*MN + idx];
    v += b1[idx % D1];
    v = (v >= 0.0f) ? v : 0.01f * v;
    g_h1[idx] = v;
}

// ---------------- two-stage BN stats -> per-channel affine ----------------
// Stage 1: grid (3, 16). Block (c, chunk) reduces rows [chunk*8, chunk*8+8) of channel c.
__global__ void stats_part_kernel(const float* __restrict__ H, int Ncols)
{
    int c = blockIdx.x, chunk = blockIdx.y;
    float s = 0.0f, sq = 0.0f;
    for (int r = chunk * 8; r < chunk * 8 + 8; r++) {
        const float* row = H + (size_t)(r * 3 + c) * Ncols;
        for (int col = threadIdx.x; col < Ncols; col += blockDim.x) {
            float v = row[col];
            s += v; sq += v * v;
        }
    }
    #pragma unroll
    for (int o = 16; o; o >>= 1) {
        s  += __shfl_xor_sync(0xffffffffu, s,  o);
        sq += __shfl_xor_sync(0xffffffffu, sq, o);
    }
    __shared__ float sh0[8], sh1[8];
    int lane = threadIdx.x & 31, wid = threadIdx.x >> 5;
    if (lane == 0) { sh0[wid] = s; sh1[wid] = sq; }
    __syncthreads();
    if (threadIdx.x < 32) {
        int nw = blockDim.x >> 5;
        s  = (lane < nw) ? sh0[lane] : 0.0f;
        sq = (lane < nw) ? sh1[lane] : 0.0f;
        #pragma unroll
        for (int o = 16; o; o >>= 1) {
            s  += __shfl_xor_sync(0xffffffffu, s,  o);
            sq += __shfl_xor_sync(0xffffffffu, sq, o);
        }
        if (lane == 0) {
            g_part[(c * 16 + chunk) * 2 + 0] = s;
            g_part[(c * 16 + chunk) * 2 + 1] = sq;
        }
    }
}

// Stage 2: tiny finisher -> affine (a = g*rsqrt(var+eps), b = beta - mean*a)
__global__ void stats_fin_kernel(int Ncols,
                                 const float* __restrict__ gamma,
                                 const float* __restrict__ beta,
                                 float* __restrict__ aff)
{
    int c = threadIdx.x;
    if (c >= 3) return;
    float s = 0.0f, sq = 0.0f;
    for (int i = 0; i < 16; i++) {
        s  += g_part[(c * 16 + i) * 2 + 0];
        sq += g_part[(c * 16 + i) * 2 + 1];
    }
    float cnt  = (float)NB * (float)Ncols;
    float mean = s / cnt;
    float var  = sq / cnt - mean * mean;
    float a = gamma[c] * rsqrtf(var + 1e-5f);
    aff[c]     = a;
    aff[3 + c] = beta[c] - mean * a;
}

// ---------------- final elementwise BN2 affine -> output ----------------
__global__ void final_kernel(float* __restrict__ out)
{
    int idx = blockIdx.x * blockDim.x + threadIdx.x;
    if (idx >= MROWS * D2) return;
    int c = (idx / D2) % 3;
    out[idx] = g_h2[idx] * g_aff2[c] + g_aff2[3 + c];
}

// ---------------- launch ----------------
extern "C" void kernel_launch(void* const* d_in, const int* in_sizes, int n_in,
                              void* d_out, int out_size)
{
    const float* x      = (const float*)d_in[0];
    const int*   coords = (const int*)  d_in[1];
    const float* mask   = (const float*)d_in[2];
    const float* W1     = (const float*)d_in[3];
    const float* b1     = (const float*)d_in[4];
    const float* g1     = (const float*)d_in[5];
    const float* be1    = (const float*)d_in[6];
    const float* W2     = (const float*)d_in[7];
    const float* b2     = (const float*)d_in[8];
    const float* g2     = (const float*)d_in[9];
    const float* be2    = (const float*)d_in[10];
    float* out = (float*)d_out;

    static float *p_s = nullptr, *p_hp, *p_h1, *p_h2, *p_a1, *p_a2;
    if (!p_s) {
        cudaGetSymbolAddress((void**)&p_s,  g_s);
        cudaGetSymbolAddress((void**)&p_hp, g_hp);
        cudaGetSymbolAddress((void**)&p_h1, g_h1);
        cudaGetSymbolAddress((void**)&p_h2, g_h2);
        cudaGetSymbolAddress((void**)&p_a1, g_aff1);
        cudaGetSymbolAddress((void**)&p_a2, g_aff2);
    }

    // 1) gather + mask
    gather_kernel<<<(MROWS*LL + 255) / 256, 256>>>(x, coords, mask);

    // 2) GEMM1 split-K: hp[z] = s * W1^T (K slice)
    dim3 grid1((D1 + BN - 1) / BN, MROWS / BM, SPLITK);
    gemm_tn<<<grid1, 256>>>(p_s, LL, W1, LL, D1,
                            p_hp, D1, LL, KCHUNK, (size_t)MROWS * D1,
                            nullptr, nullptr, 0);

    // 3) combine + b1 + leaky -> h1
    combine_kernel<<<(MROWS*D1 + 255) / 256, 256>>>(b1);

    // 4) BN1 stats -> affine1
    stats_part_kernel<<<dim3(3, 16), 256>>>(p_h1, D1);
    stats_fin_kernel<<<1, 32>>>(D1, g1, be1, p_a1);

    // 5) GEMM2 with BN1-affine on load, +b2, leaky -> h2
    dim3 grid2((D2 + BN - 1) / BN, MROWS / BM, 1);
    gemm_tn<<<grid2, 256>>>(p_h1, D1, W2, D1, D2,
                            p_h2, D2, D1, D1, 0,
                            p_a1, b2, 1);

    // 6) BN2 stats -> affine2
    stats_part_kernel<<<dim3(3, 16), 256>>>(p_h2, D2);
    stats_fin_kernel<<<1, 32>>>(D2, g2, be2, p_a2);

    // 7) final affine -> out
    final_kernel<<<(MROWS*D2 + 255) / 256, 256>>>(out);
}

// round 5
// speedup vs baseline: 2.0191x; 2.0191x over previous
#include <cuda_runtime.h>
#include <cuda_bf16.h>
#include <cstdint>

// ---------------- problem constants ----------------
#define NB   128
#define CCH  3
#define HH   128
#define WW   128
#define LL   4096
#define D1   1204
#define D2   4816
#define MROWS (NB*CCH)          // 384
#define K2P  1216               // D1 padded to multiple of 32 (and 64) for GEMM2
#define SPLITK 4
#define K1CHUNK (LL/SPLITK)     // 1024

// GEMM tile
#define TM 128
#define TN 128
#define TKC 32                  // K per mainloop iter
#define ROWH 40                 // smem row stride in halves (32 + 8 pad)

// smem: per stage 4 tiles (Ahi, Alo, Bhi, Blo) of 128 rows x ROWH halves
#define TILE_H   (128*ROWH)     // 5120 halves
#define A_HI_H   0
#define A_LO_H   (TILE_H)
#define B_HI_H   (2*TILE_H)
#define B_LO_H   (3*TILE_H)
#define STAGE_H  (4*TILE_H)     // 20480 halves
#define SMEM_BYTES (2*STAGE_H*2)  // 81920 bytes

// ---------------- device scratch ----------------
__device__ __align__(16) __nv_bfloat16 g_shi[MROWS*LL];
__device__ __align__(16) __nv_bfloat16 g_slo[MROWS*LL];
__device__ __align__(16) __nv_bfloat16 g_w1hi[D1*LL];
__device__ __align__(16) __nv_bfloat16 g_w1lo[D1*LL];
__device__ __align__(16) __nv_bfloat16 g_w2hi[D2*K2P];
__device__ __align__(16) __nv_bfloat16 g_w2lo[D2*K2P];
__device__ __align__(16) __nv_bfloat16 g_h1hi[MROWS*K2P];
__device__ __align__(16) __nv_bfloat16 g_h1lo[MROWS*K2P];
__device__ __align__(16) float g_hp[SPLITK*MROWS*D1];
__device__ __align__(16) float g_h1[MROWS*D1];
__device__ __align__(16) float g_h2[MROWS*D2];
__device__ float g_aff1[6];
__device__ float g_aff2[6];
__device__ float g_part[3*64*2];

// ---------------- PTX helpers (all baseline sm_80+ features) ----------------
__device__ __forceinline__ uint32_t smem_to_u32(const void* p) {
    uint32_t a;
    asm("{ .reg .u64 t; cvta.to.shared.u64 t, %1; cvt.u32.u64 %0, t; }" : "=r"(a) : "l"(p));
    return a;
}
__device__ __forceinline__ void cp16(uint32_t saddr, const void* g, int bytes) {
    asm volatile("cp.async.cg.shared.global [%0], [%1], 16, %2;"
                 :: "r"(saddr), "l"(g), "r"(bytes));
}
#define CP_COMMIT() asm volatile("cp.async.commit_group;" ::: "memory")
#define CP_WAIT(N)  asm volatile("cp.async.wait_group %0;" :: "n"(N) : "memory")

__device__ __forceinline__ void ldsm4(uint32_t* r, uint32_t addr) {
    asm volatile("ldmatrix.sync.aligned.m8n8.x4.shared.b16 {%0,%1,%2,%3}, [%4];"
        : "=r"(r[0]), "=r"(r[1]), "=r"(r[2]), "=r"(r[3]) : "r"(addr));
}
__device__ __forceinline__ void mma_bf16(float* c, const uint32_t* a, const uint32_t* b) {
    asm volatile(
        "mma.sync.aligned.m16n8k16.row.col.f32.bf16.bf16.f32 "
        "{%0,%1,%2,%3}, {%4,%5,%6,%7}, {%8,%9}, {%0,%1,%2,%3};"
        : "+f"(c[0]), "+f"(c[1]), "+f"(c[2]), "+f"(c[3])
        : "r"(a[0]), "r"(a[1]), "r"(a[2]), "r"(a[3]), "r"(b[0]), "r"(b[1]));
}

// ---------------- gather + mask + bf16 hi/lo split ----------------
__global__ void gather_kernel(const float* __restrict__ x,
                              const int*   __restrict__ coords,
                              const float* __restrict__ mask)
{
    int idx = blockIdx.x * blockDim.x + threadIdx.x;
    if (idx >= MROWS * LL) return;
    int l = idx & (LL - 1);
    int m = idx >> 12;
    int n = m / 3;
    int off = coords[2*l] * WW + coords[2*l + 1];
    float v = x[(size_t)m * (HH*WW) + off];
    if (mask[(size_t)n * LL + l] < 0.3f) v = 0.0f;
    __nv_bfloat16 hi = __float2bfloat16(v);
    g_shi[idx] = hi;
    g_slo[idx] = __float2bfloat16(v - __bfloat162float(hi));
}

// ---------------- fp32 -> bf16 hi/lo split with K padding ----------------
__global__ void convert_split_kernel(const float* __restrict__ in, int K, int ldOut,
                                     __nv_bfloat16* __restrict__ hi,
                                     __nv_bfloat16* __restrict__ lo, long total)
{
    long idx = (long)blockIdx.x * blockDim.x + threadIdx.x;
    if (idx >= total) return;
    int r = (int)(idx / ldOut);
    int c = (int)(idx % ldOut);
    float v = (c < K) ? in[(size_t)r * K + c] : 0.0f;
    __nv_bfloat16 h = __float2bfloat16(v);
    hi[idx] = h;
    lo[idx] = __float2bfloat16(v - __bfloat162float(h));
}

// ---------------- h1 (fp32) -> BN1-affine -> bf16 hi/lo, padded to K2P ----------------
__global__ void convert_h1_kernel()
{
    int idx = blockIdx.x * blockDim.x + threadIdx.x;
    if (idx >= MROWS * K2P) return;
    int r = idx / K2P;
    int c = idx % K2P;
    float v = 0.0f;
    if (c < D1) {
        int ch = r % 3;
        v = g_h1[(size_t)r * D1 + c] * g_aff1[ch] + g_aff1[3 + ch];
    }
    __nv_bfloat16 h = __float2bfloat16(v);
    g_h1hi[idx] = h;
    g_h1lo[idx] = __float2bfloat16(v - __bfloat162float(h));
}

// ---------------- mma.sync bf16x3 GEMM: C = A * B^T (both K-major) ----------------
// CTA tile 128x128, BK=32, 256 threads (8 warps, 2x4), warp tile 64x32.
// cp.async double-buffered. blockIdx.z = split-K slice.
__global__ __launch_bounds__(256)
void gemm_bf16x3(const __nv_bfloat16* __restrict__ Ahi, const __nv_bfloat16* __restrict__ Alo, int lda,
                 const __nv_bfloat16* __restrict__ Bhi, const __nv_bfloat16* __restrict__ Blo,
                 int ldb, int Brows,
                 float* __restrict__ C, int Ncols, int ldc,
                 int kLen, size_t zStride,
                 const float* __restrict__ colBias, int applyLeaky)
{
    extern __shared__ __align__(16) __nv_bfloat16 smem[];
    uint32_t smem_u32 = smem_to_u32(smem);

    int tid  = threadIdx.x;
    int wid  = tid >> 5;
    int lane = tid & 31;
    int m0 = blockIdx.y * TM;
    int n0 = blockIdx.x * TN;
    C += (size_t)blockIdx.z * zStride;
    int k0 = blockIdx.z * kLen;
    int nIter = kLen / TKC;

    int wm = (wid & 1) * 64;   // warp m offset in tile
    int wn = (wid >> 1) * 32;  // warp n offset in tile

    float acc[4][4][4];
    #pragma unroll
    for (int i = 0; i < 4; i++)
        #pragma unroll
        for (int j = 0; j < 4; j++)
            #pragma unroll
            for (int q = 0; q < 4; q++) acc[i][j][q] = 0.0f;

    // -------- stage loader: 4 tiles x 512 16B-chunks, 256 threads x 2 --------
    auto load_stage = [&](int stage, int kt) {
        int kbase = k0 + kt * TKC;
        uint32_t sbase = smem_u32 + (uint32_t)stage * STAGE_H * 2;
        #pragma unroll
        for (int i = 0; i < 2; i++) {
            int c = tid + i * 256;          // 0..511
            int row = c >> 2;               // 0..127
            int c16 = c & 3;                // 16B chunk within 32 halves
            uint32_t so = (uint32_t)(row * ROWH + c16 * 8) * 2;
            size_t ao = (size_t)(m0 + row) * lda + kbase + c16 * 8;
            cp16(sbase + A_HI_H*2 + so, Ahi + ao, 16);
            cp16(sbase + A_LO_H*2 + so, Alo + ao, 16);
            int brow = n0 + row;
            int bytes = (brow < Brows) ? 16 : 0;
            int rcl = brow < Brows ? brow : (Brows - 1);
            size_t bo = (size_t)rcl * ldb + kbase + c16 * 8;
            cp16(sbase + B_HI_H*2 + so, Bhi + bo, bytes);
            cp16(sbase + B_LO_H*2 + so, Blo + bo, bytes);
        }
    };

    load_stage(0, 0);
    CP_COMMIT();

    for (int kt = 0; kt < nIter; kt++) {
        if (kt + 1 < nIter) {
            load_stage((kt + 1) & 1, kt + 1);
            CP_COMMIT();
            CP_WAIT(1);
        } else {
            CP_WAIT(0);
        }
        __syncthreads();

        uint32_t sbase = smem_u32 + (uint32_t)(kt & 1) * STAGE_H * 2;
        #pragma unroll
        for (int kk = 0; kk < TKC; kk += 16) {
            uint32_t ah[4][4], al[4][4], bh[4][2], bl[4][2];
            // A frags: lanes 0-15 -> rows 0-15 @ kk, lanes 16-31 -> rows 0-15 @ kk+8
            int rowA = lane & 15;
            int colA = (lane >> 4) * 8;
            #pragma unroll
            for (int mi = 0; mi < 4; mi++) {
                uint32_t off = (uint32_t)((wm + mi*16 + rowA) * ROWH + kk + colA) * 2;
                ldsm4(ah[mi], sbase + A_HI_H*2 + off);
                ldsm4(al[mi], sbase + A_LO_H*2 + off);
            }
            // B frags: one x4 covers 16 n-rows (two n8 frags): regs {r0,r2},{r1,r3}
            int r8  = lane & 7;
            int grp = lane >> 3;
            int rowB = ((grp & 1) << 3) + r8;
            int colB = (grp >> 1) * 8;
            #pragma unroll
            for (int nh = 0; nh < 2; nh++) {
                uint32_t off = (uint32_t)((wn + nh*16 + rowB) * ROWH + kk + colB) * 2;
                uint32_t t[4];
                ldsm4(t, sbase + B_HI_H*2 + off);
                bh[nh*2][0] = t[0]; bh[nh*2][1] = t[2];
                bh[nh*2+1][0] = t[1]; bh[nh*2+1][1] = t[3];
                ldsm4(t, sbase + B_LO_H*2 + off);
                bl[nh*2][0] = t[0]; bl[nh*2][1] = t[2];
                bl[nh*2+1][0] = t[1]; bl[nh*2+1][1] = t[3];
            }
            #pragma unroll
            for (int mi = 0; mi < 4; mi++)
                #pragma unroll
                for (int ni = 0; ni < 4; ni++) {
                    mma_bf16(acc[mi][ni], ah[mi], bh[ni]);
                    mma_bf16(acc[mi][ni], ah[mi], bl[ni]);
                    mma_bf16(acc[mi][ni], al[mi], bh[ni]);
                }
        }
        __syncthreads();
    }

    // -------- epilogue --------
    #pragma unroll
    for (int mi = 0; mi < 4; mi++) {
        int r0 = m0 + wm + mi*16 + (lane >> 2);
        #pragma unroll
        for (int ni = 0; ni < 4; ni++) {
            int c0 = n0 + wn + ni*8 + (lane & 3)*2;
            #pragma unroll
            for (int q = 0; q < 4; q++) {
                int rr = r0 + ((q >> 1) << 3);   // +8 for q=2,3
                int cc = c0 + (q & 1);
                if (cc < Ncols) {
                    float v = acc[mi][ni][q];
                    if (colBias) v += colBias[cc];
                    if (applyLeaky) v = (v >= 0.0f) ? v : 0.01f * v;
                    C[(size_t)rr * ldc + cc] = v;
                }
            }
        }
    }
}

// ---------------- splitK combine + bias + leaky -> h1 (fp32) ----------------
__global__ void combine_kernel(const float* __restrict__ b1)
{
    int idx = blockIdx.x * blockDim.x + threadIdx.x;
    if (idx >= MROWS * D1) return;
    const int MN = MROWS * D1;
    float v = g_hp[idx] + g_hp[MN + idx] + g_hp[2*MN + idx] + g_hp[3*MN + idx];
    v += b1[idx % D1];
    v = (v >= 0.0f) ? v : 0.01f * v;
    g_h1[idx] = v;
}

// ---------------- BN stats stage 1: grid (3, 64), 2 rows per block ----------------
__global__ void stats_part_kernel(const float* __restrict__ H, int Ncols)
{
    int c = blockIdx.x, chunk = blockIdx.y;
    float s = 0.0f, sq = 0.0f;
    int nc4 = Ncols >> 2;
    for (int r = chunk * 2; r < chunk * 2 + 2; r++) {
        const float* row = H + (size_t)(r * 3 + c) * Ncols;
        const float4* row4 = reinterpret_cast<const float4*>(row);
        for (int col = threadIdx.x; col < nc4; col += blockDim.x) {
            float4 v = row4[col];
            s  += v.x + v.y + v.z + v.w;
            sq += v.x*v.x + v.y*v.y + v.z*v.z + v.w*v.w;
        }
        for (int col = (nc4 << 2) + threadIdx.x; col < Ncols; col += blockDim.x) {
            float v = row[col];
            s += v; sq += v * v;
        }
    }
    #pragma unroll
    for (int o = 16; o; o >>= 1) {
        s  += __shfl_xor_sync(0xffffffffu, s,  o);
        sq += __shfl_xor_sync(0xffffffffu, sq, o);
    }
    __shared__ float sh0[8], sh1[8];
    int lane = threadIdx.x & 31, wid = threadIdx.x >> 5;
    if (lane == 0) { sh0[wid] = s; sh1[wid] = sq; }
    __syncthreads();
    if (threadIdx.x < 32) {
        int nw = blockDim.x >> 5;
        s  = (lane < nw) ? sh0[lane] : 0.0f;
        sq = (lane < nw) ? sh1[lane] : 0.0f;
        #pragma unroll
        for (int o = 16; o; o >>= 1) {
            s  += __shfl_xor_sync(0xffffffffu, s,  o);
            sq += __shfl_xor_sync(0xffffffffu, sq, o);
        }
        if (lane == 0) {
            g_part[(c * 64 + chunk) * 2 + 0] = s;
            g_part[(c * 64 + chunk) * 2 + 1] = sq;
        }
    }
}

__global__ void stats_fin_kernel(int Ncols,
                                 const float* __restrict__ gamma,
                                 const float* __restrict__ beta,
                                 float* __restrict__ aff)
{
    int c = threadIdx.x;
    if (c >= 3) return;
    float s = 0.0f, sq = 0.0f;
    for (int i = 0; i < 64; i++) {
        s  += g_part[(c * 64 + i) * 2 + 0];
        sq += g_part[(c * 64 + i) * 2 + 1];
    }
    float cnt  = (float)NB * (float)Ncols;
    float mean = s / cnt;
    float var  = sq / cnt - mean * mean;
    float a = gamma[c] * rsqrtf(var + 1e-5f);
    aff[c]     = a;
    aff[3 + c] = beta[c] - mean * a;
}

// ---------------- final elementwise BN2 affine -> output ----------------
__global__ void final_kernel(float* __restrict__ out)
{
    int idx = blockIdx.x * blockDim.x + threadIdx.x;
    if (idx >= MROWS * D2) return;
    int c = (idx / D2) % 3;
    out[idx] = g_h2[idx] * g_aff2[c] + g_aff2[3 + c];
}

// ---------------- launch ----------------
extern "C" void kernel_launch(void* const* d_in, const int* in_sizes, int n_in,
                              void* d_out, int out_size)
{
    const float* x      = (const float*)d_in[0];
    const int*   coords = (const int*)  d_in[1];
    const float* mask   = (const float*)d_in[2];
    const float* W1     = (const float*)d_in[3];
    const float* b1     = (const float*)d_in[4];
    const float* g1     = (const float*)d_in[5];
    const float* be1    = (const float*)d_in[6];
    const float* W2     = (const float*)d_in[7];
    const float* b2     = (const float*)d_in[8];
    const float* g2     = (const float*)d_in[9];
    const float* be2    = (const float*)d_in[10];
    float* out = (float*)d_out;

    static bool inited = false;
    static __nv_bfloat16 *p_shi, *p_slo, *p_w1hi, *p_w1lo, *p_w2hi, *p_w2lo, *p_h1hi, *p_h1lo;
    static float *p_hp, *p_h1, *p_h2, *p_a1, *p_a2;
    if (!inited) {
        cudaGetSymbolAddress((void**)&p_shi,  g_shi);
        cudaGetSymbolAddress((void**)&p_slo,  g_slo);
        cudaGetSymbolAddress((void**)&p_w1hi, g_w1hi);
        cudaGetSymbolAddress((void**)&p_w1lo, g_w1lo);
        cudaGetSymbolAddress((void**)&p_w2hi, g_w2hi);
        cudaGetSymbolAddress((void**)&p_w2lo, g_w2lo);
        cudaGetSymbolAddress((void**)&p_h1hi, g_h1hi);
        cudaGetSymbolAddress((void**)&p_h1lo, g_h1lo);
        cudaGetSymbolAddress((void**)&p_hp,   g_hp);
        cudaGetSymbolAddress((void**)&p_h1,   g_h1);
        cudaGetSymbolAddress((void**)&p_h2,   g_h2);
        cudaGetSymbolAddress((void**)&p_a1,   g_aff1);
        cudaGetSymbolAddress((void**)&p_a2,   g_aff2);
        cudaFuncSetAttribute(gemm_bf16x3, cudaFuncAttributeMaxDynamicSharedMemorySize, SMEM_BYTES);
        inited = true;
    }

    // 1) gather + mask + split -> s hi/lo
    gather_kernel<<<(MROWS*LL + 255) / 256, 256>>>(x, coords, mask);

    // 2) W1, W2 -> bf16 hi/lo (W2 K-padded to 1216)
    {
        long t1 = (long)D1 * LL;
        convert_split_kernel<<<(unsigned)((t1 + 255) / 256), 256>>>(W1, LL, LL, p_w1hi, p_w1lo, t1);
        long t2 = (long)D2 * K2P;
        convert_split_kernel<<<(unsigned)((t2 + 255) / 256), 256>>>(W2, D1, K2P, p_w2hi, p_w2lo, t2);
    }

    // 3) GEMM1 split-K: hp[z] = s * W1^T (K slice)
    {
        dim3 grid((D1 + TN - 1) / TN, MROWS / TM, SPLITK);   // (10, 3, 4)
        gemm_bf16x3<<<grid, 256, SMEM_BYTES>>>(
            p_shi, p_slo, LL,
            p_w1hi, p_w1lo, LL, D1,
            p_hp, D1, D1,
            K1CHUNK, (size_t)MROWS * D1,
            nullptr, 0);
    }

    // 4) combine + b1 + leaky -> h1 (fp32)
    combine_kernel<<<(MROWS*D1 + 255) / 256, 256>>>(b1);

    // 5) BN1 stats -> affine1; fold into bf16 conversion of h1
    stats_part_kernel<<<dim3(3, 64), 256>>>(p_h1, D1);
    stats_fin_kernel<<<1, 32>>>(D1, g1, be1, p_a1);
    convert_h1_kernel<<<(MROWS*K2P + 255) / 256, 256>>>();

    // 6) GEMM2: h2 = leaky(h1n * W2^T + b2)
    {
        dim3 grid((D2 + TN - 1) / TN, MROWS / TM, 1);        // (38, 3, 1)
        gemm_bf16x3<<<grid, 256, SMEM_BYTES>>>(
            p_h1hi, p_h1lo, K2P,
            p_w2hi, p_w2lo, K2P, D2,
            p_h2, D2, D2,
            K2P, 0,
            b2, 1);
    }

    // 7) BN2 stats -> affine2
    stats_part_kernel<<<dim3(3, 64), 256>>>(p_h2, D2);
    stats_fin_kernel<<<1, 32>>>(D2, g2, be2, p_a2);

    // 8) final affine -> out
    final_kernel<<<(MROWS*D2 + 255) / 256, 256>>>(out);
}

// round 6
// speedup vs baseline: 2.4140x; 1.1956x over previous
#include <cuda_runtime.h>
#include <cuda_bf16.h>
#include <cstdint>

// ---------------- problem constants ----------------
#define NB   128
#define CCH  3
#define HH   128
#define WW   128
#define LL   4096
#define D1   1204
#define D2   4816
#define MROWS (NB*CCH)          // 384
#define K2P  1216               // D1 padded
#define SPLITK 4
#define K1CHUNK (LL/SPLITK)     // 1024

// GEMM tile
#define TM 128
#define TN 128
#define TKC 32
#define ROWH 40                 // smem row stride in halves (32 + 8 pad)
#define NSTAGES 3

#define TILE_H   (128*ROWH)     // 5120 halves
#define A_HI_H   0
#define A_LO_H   (TILE_H)
#define B_HI_H   (2*TILE_H)
#define B_LO_H   (3*TILE_H)
#define STAGE_H  (4*TILE_H)     // 20480 halves = 40960 B
#define SMEM_BYTES (NSTAGES*STAGE_H*2)   // 122880 B

// ---------------- device scratch ----------------
__device__ __align__(16) __nv_bfloat16 g_shi[MROWS*LL];
__device__ __align__(16) __nv_bfloat16 g_slo[MROWS*LL];
__device__ __align__(16) __nv_bfloat16 g_w1hi[D1*LL];
__device__ __align__(16) __nv_bfloat16 g_w1lo[D1*LL];
__device__ __align__(16) __nv_bfloat16 g_w2hi[D2*K2P];
__device__ __align__(16) __nv_bfloat16 g_w2lo[D2*K2P];
__device__ __align__(16) __nv_bfloat16 g_h1hi[MROWS*K2P];
__device__ __align__(16) __nv_bfloat16 g_h1lo[MROWS*K2P];
__device__ __align__(16) float g_hp[SPLITK*MROWS*D1];
__device__ __align__(16) float g_h1[MROWS*D1];
__device__ __align__(16) float g_h2[MROWS*D2];
__device__ float g_aff1[6];
__device__ float g_aff2[6];
__device__ float g_part[3*64*2];

// ---------------- PTX helpers ----------------
__device__ __forceinline__ uint32_t smem_to_u32(const void* p) {
    uint32_t a;
    asm("{ .reg .u64 t; cvta.to.shared.u64 t, %1; cvt.u32.u64 %0, t; }" : "=r"(a) : "l"(p));
    return a;
}
__device__ __forceinline__ void cp16(uint32_t saddr, const void* g, int bytes) {
    asm volatile("cp.async.cg.shared.global [%0], [%1], 16, %2;"
                 :: "r"(saddr), "l"(g), "r"(bytes));
}
#define CP_COMMIT() asm volatile("cp.async.commit_group;" ::: "memory")
#define CP_WAIT(N)  asm volatile("cp.async.wait_group %0;" :: "n"(N) : "memory")

__device__ __forceinline__ void ldsm4(uint32_t* r, uint32_t addr) {
    asm volatile("ldmatrix.sync.aligned.m8n8.x4.shared.b16 {%0,%1,%2,%3}, [%4];"
        : "=r"(r[0]), "=r"(r[1]), "=r"(r[2]), "=r"(r[3]) : "r"(addr));
}
__device__ __forceinline__ void mma_bf16(float* c, const uint32_t* a, const uint32_t* b) {
    asm volatile(
        "mma.sync.aligned.m16n8k16.row.col.f32.bf16.bf16.f32 "
        "{%0,%1,%2,%3}, {%4,%5,%6,%7}, {%8,%9}, {%0,%1,%2,%3};"
        : "+f"(c[0]), "+f"(c[1]), "+f"(c[2]), "+f"(c[3])
        : "r"(a[0]), "r"(a[1]), "r"(a[2]), "r"(a[3]), "r"(b[0]), "r"(b[1]));
}

// pack 4 floats -> hi (4 bf16) and lo (4 bf16) as uint2 each
__device__ __forceinline__ void split4(const float* v, uint2& hiu, uint2& lou) {
    __nv_bfloat16 h[4], l[4];
    #pragma unroll
    for (int j = 0; j < 4; j++) {
        h[j] = __float2bfloat16(v[j]);
        l[j] = __float2bfloat16(v[j] - __bfloat162float(h[j]));
    }
    hiu.x = (uint32_t)__bfloat16_as_ushort(h[0]) | ((uint32_t)__bfloat16_as_ushort(h[1]) << 16);
    hiu.y = (uint32_t)__bfloat16_as_ushort(h[2]) | ((uint32_t)__bfloat16_as_ushort(h[3]) << 16);
    lou.x = (uint32_t)__bfloat16_as_ushort(l[0]) | ((uint32_t)__bfloat16_as_ushort(l[1]) << 16);
    lou.y = (uint32_t)__bfloat16_as_ushort(l[2]) | ((uint32_t)__bfloat16_as_ushort(l[3]) << 16);
}

// ---------------- gather + mask + bf16 hi/lo split ----------------
__global__ void gather_kernel(const float* __restrict__ x,
                              const int*   __restrict__ coords,
                              const float* __restrict__ mask)
{
    int idx = blockIdx.x * blockDim.x + threadIdx.x;
    if (idx >= MROWS * LL) return;
    int l = idx & (LL - 1);
    int m = idx >> 12;
    int n = m / 3;
    int off = coords[2*l] * WW + coords[2*l + 1];
    float v = x[(size_t)m * (HH*WW) + off];
    if (mask[(size_t)n * LL + l] < 0.3f) v = 0.0f;
    __nv_bfloat16 hi = __float2bfloat16(v);
    g_shi[idx] = hi;
    g_slo[idx] = __float2bfloat16(v - __bfloat162float(hi));
}

// ---------------- fp32 -> bf16 hi/lo, vectorized x4, K padded to ldOut ----------------
__global__ void convert_split_kernel(const float* __restrict__ in, int K, int ldOut,
                                     __nv_bfloat16* __restrict__ hi,
                                     __nv_bfloat16* __restrict__ lo, long total4)
{
    long i4 = (long)blockIdx.x * blockDim.x + threadIdx.x;
    if (i4 >= total4) return;
    long idx = i4 * 4;
    int r = (int)(idx / ldOut);
    int c = (int)(idx % ldOut);
    float v[4];
    if (c + 3 < K) {
        float4 f = *reinterpret_cast<const float4*>(in + (size_t)r * K + c);
        v[0] = f.x; v[1] = f.y; v[2] = f.z; v[3] = f.w;
    } else {
        #pragma unroll
        for (int j = 0; j < 4; j++)
            v[j] = (c + j < K) ? in[(size_t)r * K + c + j] : 0.0f;
    }
    uint2 hu, lu;
    split4(v, hu, lu);
    *reinterpret_cast<uint2*>(hi + idx) = hu;
    *reinterpret_cast<uint2*>(lo + idx) = lu;
}

// ---------------- h1 -> BN1 affine -> bf16 hi/lo, padded to K2P, x4 ----------------
__global__ void convert_h1_kernel()
{
    int i4 = blockIdx.x * blockDim.x + threadIdx.x;
    if (i4 >= MROWS * K2P / 4) return;
    int idx = i4 * 4;
    int r = idx / K2P;
    int c = idx % K2P;
    int ch = r % 3;
    float a = g_aff1[ch], b = g_aff1[3 + ch];
    float v[4] = {0.0f, 0.0f, 0.0f, 0.0f};
    if (c + 3 < D1) {
        float4 f = *reinterpret_cast<const float4*>(g_h1 + (size_t)r * D1 + c);
        v[0] = f.x * a + b; v[1] = f.y * a + b; v[2] = f.z * a + b; v[3] = f.w * a + b;
    } else {
        #pragma unroll
        for (int j = 0; j < 4; j++)
            if (c + j < D1) v[j] = g_h1[(size_t)r * D1 + c + j] * a + b;
    }
    uint2 hu, lu;
    split4(v, hu, lu);
    *reinterpret_cast<uint2*>(g_h1hi + idx) = hu;
    *reinterpret_cast<uint2*>(g_h1lo + idx) = lu;
}

// ---------------- mma.sync bf16x3 GEMM: C = A * B^T ----------------
// CTA 128x128, 512 threads (16 warps 4x4, warp tile 32x32), BK=32, 3-stage cp.async.
__global__ __launch_bounds__(512)
void gemm_bf16x3(const __nv_bfloat16* __restrict__ Ahi, const __nv_bfloat16* __restrict__ Alo, int lda,
                 const __nv_bfloat16* __restrict__ Bhi, const __nv_bfloat16* __restrict__ Blo,
                 int ldb, int Brows,
                 float* __restrict__ C, int Ncols, int ldc,
                 int kLen, size_t zStride,
                 const float* __restrict__ colBias, int applyLeaky)
{
    extern __shared__ __align__(16) __nv_bfloat16 smem[];
    uint32_t smem_u32 = smem_to_u32(smem);

    int tid  = threadIdx.x;
    int wid  = tid >> 5;
    int lane = tid & 31;
    int m0 = blockIdx.y * TM;
    int n0 = blockIdx.x * TN;
    C += (size_t)blockIdx.z * zStride;
    int k0 = blockIdx.z * kLen;
    int nIter = kLen / TKC;

    int wm = (wid & 3) * 32;
    int wn = (wid >> 2) * 32;

    float acc[2][4][4];
    #pragma unroll
    for (int i = 0; i < 2; i++)
        #pragma unroll
        for (int j = 0; j < 4; j++)
            #pragma unroll
            for (int q = 0; q < 4; q++) acc[i][j][q] = 0.0f;

    // stage loader: 4 tiles x 512 16B-chunks, 512 threads -> 1 chunk per tile per thread
    int ldRow = tid >> 2;          // 0..127
    int ldC16 = tid & 3;           // 16B chunk (8 halves)
    uint32_t ldSo = (uint32_t)(ldRow * ROWH + ldC16 * 8) * 2;
    int ldBrow = n0 + ldRow;
    int ldBbytes = (ldBrow < Brows) ? 16 : 0;
    int ldBrowCl = (ldBrow < Brows) ? ldBrow : (Brows - 1);

    auto load_stage = [&](int stage, int kt) {
        int kbase = k0 + kt * TKC;
        uint32_t sbase = smem_u32 + (uint32_t)stage * STAGE_H * 2;
        size_t ao = (size_t)(m0 + ldRow) * lda + kbase + ldC16 * 8;
        cp16(sbase + A_HI_H*2 + ldSo, Ahi + ao, 16);
        cp16(sbase + A_LO_H*2 + ldSo, Alo + ao, 16);
        size_t bo = (size_t)ldBrowCl * ldb + kbase + ldC16 * 8;
        cp16(sbase + B_HI_H*2 + ldSo, Bhi + bo, ldBbytes);
        cp16(sbase + B_LO_H*2 + ldSo, Blo + bo, ldBbytes);
    };

    load_stage(0, 0); CP_COMMIT();
    load_stage(1, 1); CP_COMMIT();

    int rowA = lane & 15;
    int colA = (lane >> 4) * 8;
    int r8  = lane & 7;
    int grp = lane >> 3;
    int rowB = ((grp & 1) << 3) + r8;
    int colB = (grp >> 1) * 8;

    for (int kt = 0; kt < nIter; kt++) {
        CP_WAIT(1);
        __syncthreads();
        if (kt + 2 < nIter) { load_stage((kt + 2) % NSTAGES, kt + 2); CP_COMMIT(); }

        uint32_t sbase = smem_u32 + (uint32_t)(kt % NSTAGES) * STAGE_H * 2;
        #pragma unroll
        for (int kk = 0; kk < TKC; kk += 16) {
            uint32_t ah[2][4], al[2][4], bh[4][2], bl[4][2];
            #pragma unroll
            for (int mi = 0; mi < 2; mi++) {
                uint32_t off = (uint32_t)((wm + mi*16 + rowA) * ROWH + kk + colA) * 2;
                ldsm4(ah[mi], sbase + A_HI_H*2 + off);
                ldsm4(al[mi], sbase + A_LO_H*2 + off);
            }
            #pragma unroll
            for (int nh = 0; nh < 2; nh++) {
                uint32_t off = (uint32_t)((wn + nh*16 + rowB) * ROWH + kk + colB) * 2;
                uint32_t t[4];
                ldsm4(t, sbase + B_HI_H*2 + off);
                bh[nh*2][0] = t[0]; bh[nh*2][1] = t[2];
                bh[nh*2+1][0] = t[1]; bh[nh*2+1][1] = t[3];
                ldsm4(t, sbase + B_LO_H*2 + off);
                bl[nh*2][0] = t[0]; bl[nh*2][1] = t[2];
                bl[nh*2+1][0] = t[1]; bl[nh*2+1][1] = t[3];
            }
            #pragma unroll
            for (int mi = 0; mi < 2; mi++)
                #pragma unroll
                for (int ni = 0; ni < 4; ni++) {
                    mma_bf16(acc[mi][ni], ah[mi], bh[ni]);
                    mma_bf16(acc[mi][ni], ah[mi], bl[ni]);
                    mma_bf16(acc[mi][ni], al[mi], bh[ni]);
                }
        }
        __syncthreads();
    }

    // -------- epilogue: float2 stores --------
    #pragma unroll
    for (int mi = 0; mi < 2; mi++) {
        int r0 = m0 + wm + mi*16 + (lane >> 2);
        #pragma unroll
        for (int ni = 0; ni < 4; ni++) {
            int c0 = n0 + wn + ni*8 + (lane & 3)*2;
            if (c0 < Ncols) {        // c0 even, Ncols even -> c0+1 < Ncols too
                float2 b2v = colBias ? *reinterpret_cast<const float2*>(colBias + c0)
                                     : make_float2(0.0f, 0.0f);
                float2 v0 = make_float2(acc[mi][ni][0] + b2v.x, acc[mi][ni][1] + b2v.y);
                float2 v1 = make_float2(acc[mi][ni][2] + b2v.x, acc[mi][ni][3] + b2v.y);
                if (applyLeaky) {
                    v0.x = (v0.x >= 0.0f) ? v0.x : 0.01f * v0.x;
                    v0.y = (v0.y >= 0.0f) ? v0.y : 0.01f * v0.y;
                    v1.x = (v1.x >= 0.0f) ? v1.x : 0.01f * v1.x;
                    v1.y = (v1.y >= 0.0f) ? v1.y : 0.01f * v1.y;
                }
                *reinterpret_cast<float2*>(C + (size_t)r0 * ldc + c0) = v0;
                *reinterpret_cast<float2*>(C + (size_t)(r0 + 8) * ldc + c0) = v1;
            }
        }
    }
}

// ---------------- splitK combine + bias + leaky -> h1 (fp32), x4 ----------------
__global__ void combine_kernel(const float* __restrict__ b1)
{
    int i4 = blockIdx.x * blockDim.x + threadIdx.x;
    if (i4 >= MROWS * D1 / 4) return;
    int idx = i4 * 4;
    const int MN = MROWS * D1;
    float4 a0 = *reinterpret_cast<const float4*>(g_hp + idx);
    float4 a1 = *reinterpret_cast<const float4*>(g_hp + MN + idx);
    float4 a2 = *reinterpret_cast<const float4*>(g_hp + 2*MN + idx);
    float4 a3 = *reinterpret_cast<const float4*>(g_hp + 3*MN + idx);
    float4 bb = *reinterpret_cast<const float4*>(b1 + (idx % D1));
    float4 v;
    v.x = a0.x + a1.x + a2.x + a3.x + bb.x;
    v.y = a0.y + a1.y + a2.y + a3.y + bb.y;
    v.z = a0.z + a1.z + a2.z + a3.z + bb.z;
    v.w = a0.w + a1.w + a2.w + a3.w + bb.w;
    v.x = (v.x >= 0.0f) ? v.x : 0.01f * v.x;
    v.y = (v.y >= 0.0f) ? v.y : 0.01f * v.y;
    v.z = (v.z >= 0.0f) ? v.z : 0.01f * v.z;
    v.w = (v.w >= 0.0f) ? v.w : 0.01f * v.w;
    *reinterpret_cast<float4*>(g_h1 + idx) = v;
}

// ---------------- BN stats stage 1: grid (3, 64), 2 rows per block ----------------
__global__ void stats_part_kernel(const float* __restrict__ H, int Ncols)
{
    int c = blockIdx.x, chunk = blockIdx.y;
    float s = 0.0f, sq = 0.0f;
    int nc4 = Ncols >> 2;
    for (int r = chunk * 2; r < chunk * 2 + 2; r++) {
        const float* row = H + (size_t)(r * 3 + c) * Ncols;
        const float4* row4 = reinterpret_cast<const float4*>(row);
        for (int col = threadIdx.x; col < nc4; col += blockDim.x) {
            float4 v = row4[col];
            s  += v.x + v.y + v.z + v.w;
            sq += v.x*v.x + v.y*v.y + v.z*v.z + v.w*v.w;
        }
        for (int col = (nc4 << 2) + threadIdx.x; col < Ncols; col += blockDim.x) {
            float v = row[col];
            s += v; sq += v * v;
        }
    }
    #pragma unroll
    for (int o = 16; o; o >>= 1) {
        s  += __shfl_xor_sync(0xffffffffu, s,  o);
        sq += __shfl_xor_sync(0xffffffffu, sq, o);
    }
    __shared__ float sh0[8], sh1[8];
    int lane = threadIdx.x & 31, wid = threadIdx.x >> 5;
    if (lane == 0) { sh0[wid] = s; sh1[wid] = sq; }
    __syncthreads();
    if (threadIdx.x < 32) {
        int nw = blockDim.x >> 5;
        s  = (lane < nw) ? sh0[lane] : 0.0f;
        sq = (lane < nw) ? sh1[lane] : 0.0f;
        #pragma unroll
        for (int o = 16; o; o >>= 1) {
            s  += __shfl_xor_sync(0xffffffffu, s,  o);
            sq += __shfl_xor_sync(0xffffffffu, sq, o);
        }
        if (lane == 0) {
            g_part[(c * 64 + chunk) * 2 + 0] = s;
            g_part[(c * 64 + chunk) * 2 + 1] = sq;
        }
    }
}

__global__ void stats_fin_kernel(int Ncols,
                                 const float* __restrict__ gamma,
                                 const float* __restrict__ beta,
                                 float* __restrict__ aff)
{
    int c = threadIdx.x;
    if (c >= 3) return;
    float s = 0.0f, sq = 0.0f;
    for (int i = 0; i < 64; i++) {
        s  += g_part[(c * 64 + i) * 2 + 0];
        sq += g_part[(c * 64 + i) * 2 + 1];
    }
    float cnt  = (float)NB * (float)Ncols;
    float mean = s / cnt;
    float var  = sq / cnt - mean * mean;
    float a = gamma[c] * rsqrtf(var + 1e-5f);
    aff[c]     = a;
    aff[3 + c] = beta[c] - mean * a;
}

// ---------------- final elementwise BN2 affine -> output, x4 ----------------
__global__ void final_kernel(float* __restrict__ out)
{
    int i4 = blockIdx.x * blockDim.x + threadIdx.x;
    if (i4 >= MROWS * D2 / 4) return;
    int idx = i4 * 4;
    int c = (idx / D2) % 3;
    float a = g_aff2[c], b = g_aff2[3 + c];
    float4 v = *reinterpret_cast<const float4*>(g_h2 + idx);
    v.x = v.x * a + b; v.y = v.y * a + b; v.z = v.z * a + b; v.w = v.w * a + b;
    *reinterpret_cast<float4*>(out + idx) = v;
}

// ---------------- launch ----------------
extern "C" void kernel_launch(void* const* d_in, const int* in_sizes, int n_in,
                              void* d_out, int out_size)
{
    const float* x      = (const float*)d_in[0];
    const int*   coords = (const int*)  d_in[1];
    const float* mask   = (const float*)d_in[2];
    const float* W1     = (const float*)d_in[3];
    const float* b1     = (const float*)d_in[4];
    const float* g1     = (const float*)d_in[5];
    const float* be1    = (const float*)d_in[6];
    const float* W2     = (const float*)d_in[7];
    const float* b2     = (const float*)d_in[8];
    const float* g2     = (const float*)d_in[9];
    const float* be2    = (const float*)d_in[10];
    float* out = (float*)d_out;

    static bool inited = false;
    static __nv_bfloat16 *p_shi, *p_slo, *p_w1hi, *p_w1lo, *p_w2hi, *p_w2lo, *p_h1hi, *p_h1lo;
    static float *p_hp, *p_h1, *p_h2, *p_a1, *p_a2;
    if (!inited) {
        cudaGetSymbolAddress((void**)&p_shi,  g_shi);
        cudaGetSymbolAddress((void**)&p_slo,  g_slo);
        cudaGetSymbolAddress((void**)&p_w1hi, g_w1hi);
        cudaGetSymbolAddress((void**)&p_w1lo, g_w1lo);
        cudaGetSymbolAddress((void**)&p_w2hi, g_w2hi);
        cudaGetSymbolAddress((void**)&p_w2lo, g_w2lo);
        cudaGetSymbolAddress((void**)&p_h1hi, g_h1hi);
        cudaGetSymbolAddress((void**)&p_h1lo, g_h1lo);
        cudaGetSymbolAddress((void**)&p_hp,   g_hp);
        cudaGetSymbolAddress((void**)&p_h1,   g_h1);
        cudaGetSymbolAddress((void**)&p_h2,   g_h2);
        cudaGetSymbolAddress((void**)&p_a1,   g_aff1);
        cudaGetSymbolAddress((void**)&p_a2,   g_aff2);
        cudaFuncSetAttribute(gemm_bf16x3, cudaFuncAttributeMaxDynamicSharedMemorySize, SMEM_BYTES);
        inited = true;
    }

    // 1) gather + mask + split -> s hi/lo
    gather_kernel<<<(MROWS*LL + 255) / 256, 256>>>(x, coords, mask);

    // 2) W1, W2 -> bf16 hi/lo (vectorized x4)
    {
        long t1 = (long)D1 * LL / 4;
        convert_split_kernel<<<(unsigned)((t1 + 255) / 256), 256>>>(W1, LL, LL, p_w1hi, p_w1lo, t1);
        long t2 = (long)D2 * K2P / 4;
        convert_split_kernel<<<(unsigned)((t2 + 255) / 256), 256>>>(W2, D1, K2P, p_w2hi, p_w2lo, t2);
    }

    // 3) GEMM1 split-K: hp[z] = s * W1^T (K slice)
    {
        dim3 grid((D1 + TN - 1) / TN, MROWS / TM, SPLITK);   // (10, 3, 4)
        gemm_bf16x3<<<grid, 512, SMEM_BYTES>>>(
            p_shi, p_slo, LL,
            p_w1hi, p_w1lo, LL, D1,
            p_hp, D1, D1,
            K1CHUNK, (size_t)MROWS * D1,
            nullptr, 0);
    }

    // 4) combine + b1 + leaky -> h1 (fp32)
    combine_kernel<<<(MROWS*D1/4 + 255) / 256, 256>>>(b1);

    // 5) BN1 stats -> affine1; fold into bf16 conversion of h1
    stats_part_kernel<<<dim3(3, 64), 256>>>(p_h1, D1);
    stats_fin_kernel<<<1, 32>>>(D1, g1, be1, p_a1);
    convert_h1_kernel<<<(MROWS*K2P/4 + 255) / 256, 256>>>();

    // 6) GEMM2: h2 = leaky(h1n * W2^T + b2)
    {
        dim3 grid((D2 + TN - 1) / TN, MROWS / TM, 1);        // (38, 3, 1)
        gemm_bf16x3<<<grid, 512, SMEM_BYTES>>>(
            p_h1hi, p_h1lo, K2P,
            p_w2hi, p_w2lo, K2P, D2,
            p_h2, D2, D2,
            K2P, 0,
            b2, 1);
    }

    // 7) BN2 stats -> affine2
    stats_part_kernel<<<dim3(3, 64), 256>>>(p_h2, D2);
    stats_fin_kernel<<<1, 32>>>(D2, g2, be2, p_a2);

    // 8) final affine -> out
    final_kernel<<<(MROWS*D2/4 + 255) / 256, 256>>>(out);
}

// round 7
// speedup vs baseline: 2.6034x; 1.0785x over previous
#include <cuda_runtime.h>
#include <cuda_bf16.h>
#include <cstdint>

// ---------------- problem constants ----------------
#define NB   128
#define CCH  3
#define HH   128
#define WW   128
#define LL   4096
#define D1   1204
#define D2   4816
#define MROWS (NB*CCH)          // 384
#define K2P  1216               // D1 padded
#define SPLITK 4
#define K1CHUNK (LL/SPLITK)     // 1024

// GEMM tile
#define TM 128
#define TN 128
#define TKC 64
#define ROWH 72                 // smem row stride in halves (64 + 8 pad)
#define NSTAGES 3

#define TILE_H   (128*ROWH)     // 9216 halves
#define A_HI_H   0
#define A_LO_H   (TILE_H)
#define B_HI_H   (2*TILE_H)
#define B_LO_H   (3*TILE_H)
#define STAGE_H  (4*TILE_H)     // 36864 halves = 73728 B
#define SMEM_BYTES (NSTAGES*STAGE_H*2)   // 221184 B

// ---------------- device scratch ----------------
__device__ __align__(16) __nv_bfloat16 g_shi[MROWS*LL];
__device__ __align__(16) __nv_bfloat16 g_slo[MROWS*LL];
__device__ __align__(16) __nv_bfloat16 g_w1hi[D1*LL];
__device__ __align__(16) __nv_bfloat16 g_w1lo[D1*LL];
__device__ __align__(16) __nv_bfloat16 g_w2hi[D2*K2P];
__device__ __align__(16) __nv_bfloat16 g_w2lo[D2*K2P];
__device__ __align__(16) __nv_bfloat16 g_h1hi[MROWS*K2P];
__device__ __align__(16) __nv_bfloat16 g_h1lo[MROWS*K2P];
__device__ __align__(16) float g_hp[SPLITK*MROWS*D1];
__device__ __align__(16) float g_h1[MROWS*D1];
__device__ __align__(16) float g_h2[MROWS*D2];
__device__ float g_aff1[6];
__device__ float g_aff2[6];
__device__ float g_part[3*64*2];

// ---------------- PTX helpers ----------------
__device__ __forceinline__ uint32_t smem_to_u32(const void* p) {
    uint32_t a;
    asm("{ .reg .u64 t; cvta.to.shared.u64 t, %1; cvt.u32.u64 %0, t; }" : "=r"(a) : "l"(p));
    return a;
}
__device__ __forceinline__ void cp16(uint32_t saddr, const void* g, int bytes) {
    asm volatile("cp.async.cg.shared.global [%0], [%1], 16, %2;"
                 :: "r"(saddr), "l"(g), "r"(bytes));
}
#define CP_COMMIT() asm volatile("cp.async.commit_group;" ::: "memory")
#define CP_WAIT(N)  asm volatile("cp.async.wait_group %0;" :: "n"(N) : "memory")

__device__ __forceinline__ void ldsm4(uint32_t* r, uint32_t addr) {
    asm volatile("ldmatrix.sync.aligned.m8n8.x4.shared.b16 {%0,%1,%2,%3}, [%4];"
        : "=r"(r[0]), "=r"(r[1]), "=r"(r[2]), "=r"(r[3]) : "r"(addr));
}
__device__ __forceinline__ void mma_bf16(float* c, const uint32_t* a, const uint32_t* b) {
    asm volatile(
        "mma.sync.aligned.m16n8k16.row.col.f32.bf16.bf16.f32 "
        "{%0,%1,%2,%3}, {%4,%5,%6,%7}, {%8,%9}, {%0,%1,%2,%3};"
        : "+f"(c[0]), "+f"(c[1]), "+f"(c[2]), "+f"(c[3])
        : "r"(a[0]), "r"(a[1]), "r"(a[2]), "r"(a[3]), "r"(b[0]), "r"(b[1]));
}

// pack 4 floats -> hi (4 bf16) and lo (4 bf16) as uint2 each
__device__ __forceinline__ void split4(const float* v, uint2& hiu, uint2& lou) {
    __nv_bfloat16 h[4], l[4];
    #pragma unroll
    for (int j = 0; j < 4; j++) {
        h[j] = __float2bfloat16(v[j]);
        l[j] = __float2bfloat16(v[j] - __bfloat162float(h[j]));
    }
    hiu.x = (uint32_t)__bfloat16_as_ushort(h[0]) | ((uint32_t)__bfloat16_as_ushort(h[1]) << 16);
    hiu.y = (uint32_t)__bfloat16_as_ushort(h[2]) | ((uint32_t)__bfloat16_as_ushort(h[3]) << 16);
    lou.x = (uint32_t)__bfloat16_as_ushort(l[0]) | ((uint32_t)__bfloat16_as_ushort(l[1]) << 16);
    lou.y = (uint32_t)__bfloat16_as_ushort(l[2]) | ((uint32_t)__bfloat16_as_ushort(l[3]) << 16);
}

// ---------------- gather + mask + bf16 hi/lo split ----------------
__global__ void gather_kernel(const float* __restrict__ x,
                              const int*   __restrict__ coords,
                              const float* __restrict__ mask)
{
    int idx = blockIdx.x * blockDim.x + threadIdx.x;
    if (idx >= MROWS * LL) return;
    int l = idx & (LL - 1);
    int m = idx >> 12;
    int n = m / 3;
    int off = coords[2*l] * WW + coords[2*l + 1];
    float v = x[(size_t)m * (HH*WW) + off];
    if (mask[(size_t)n * LL + l] < 0.3f) v = 0.0f;
    __nv_bfloat16 hi = __float2bfloat16(v);
    g_shi[idx] = hi;
    g_slo[idx] = __float2bfloat16(v - __bfloat162float(hi));
}

// ---------------- fp32 -> bf16 hi/lo, vectorized x4, K padded to ldOut ----------------
__global__ void convert_split_kernel(const float* __restrict__ in, int K, int ldOut,
                                     __nv_bfloat16* __restrict__ hi,
                                     __nv_bfloat16* __restrict__ lo, long total4)
{
    long i4 = (long)blockIdx.x * blockDim.x + threadIdx.x;
    if (i4 >= total4) return;
    long idx = i4 * 4;
    int r = (int)(idx / ldOut);
    int c = (int)(idx % ldOut);
    float v[4];
    if (c + 3 < K) {
        float4 f = *reinterpret_cast<const float4*>(in + (size_t)r * K + c);
        v[0] = f.x; v[1] = f.y; v[2] = f.z; v[3] = f.w;
    } else {
        #pragma unroll
        for (int j = 0; j < 4; j++)
            v[j] = (c + j < K) ? in[(size_t)r * K + c + j] : 0.0f;
    }
    uint2 hu, lu;
    split4(v, hu, lu);
    *reinterpret_cast<uint2*>(hi + idx) = hu;
    *reinterpret_cast<uint2*>(lo + idx) = lu;
}

// ---------------- h1 -> BN1 affine -> bf16 hi/lo, padded to K2P, x4 ----------------
__global__ void convert_h1_kernel()
{
    int i4 = blockIdx.x * blockDim.x + threadIdx.x;
    if (i4 >= MROWS * K2P / 4) return;
    int idx = i4 * 4;
    int r = idx / K2P;
    int c = idx % K2P;
    int ch = r % 3;
    float a = g_aff1[ch], b = g_aff1[3 + ch];
    float v[4] = {0.0f, 0.0f, 0.0f, 0.0f};
    if (c + 3 < D1) {
        float4 f = *reinterpret_cast<const float4*>(g_h1 + (size_t)r * D1 + c);
        v[0] = f.x * a + b; v[1] = f.y * a + b; v[2] = f.z * a + b; v[3] = f.w * a + b;
    } else {
        #pragma unroll
        for (int j = 0; j < 4; j++)
            if (c + j < D1) v[j] = g_h1[(size_t)r * D1 + c + j] * a + b;
    }
    uint2 hu, lu;
    split4(v, hu, lu);
    *reinterpret_cast<uint2*>(g_h1hi + idx) = hu;
    *reinterpret_cast<uint2*>(g_h1lo + idx) = lu;
}

// ---------------- mma.sync bf16x3 GEMM: C = A * B^T ----------------
// CTA 128x128, 512 threads (16 warps 4x4, warp 32x32), BK=64, 3-stage cp.async.
// Split accumulators: acc_h for hi*hi, acc_l for the two correction terms.
__global__ __launch_bounds__(512)
void gemm_bf16x3(const __nv_bfloat16* __restrict__ Ahi, const __nv_bfloat16* __restrict__ Alo, int lda,
                 const __nv_bfloat16* __restrict__ Bhi, const __nv_bfloat16* __restrict__ Blo,
                 int ldb, int Brows,
                 float* __restrict__ C, int Ncols, int ldc,
                 int kLen, size_t zStride,
                 const float* __restrict__ colBias, int applyLeaky)
{
    extern __shared__ __align__(16) __nv_bfloat16 smem[];
    uint32_t smem_u32 = smem_to_u32(smem);

    int tid  = threadIdx.x;
    int wid  = tid >> 5;
    int lane = tid & 31;
    int m0 = blockIdx.y * TM;
    int n0 = blockIdx.x * TN;
    C += (size_t)blockIdx.z * zStride;
    int k0 = blockIdx.z * kLen;
    int nIter = kLen / TKC;

    int wm = (wid & 3) * 32;
    int wn = (wid >> 2) * 32;

    float acc_h[2][4][4], acc_l[2][4][4];
    #pragma unroll
    for (int i = 0; i < 2; i++)
        #pragma unroll
        for (int j = 0; j < 4; j++)
            #pragma unroll
            for (int q = 0; q < 4; q++) { acc_h[i][j][q] = 0.0f; acc_l[i][j][q] = 0.0f; }

    // loader: 4 tiles x 1024 16B-chunks, 512 threads -> 2 chunks per tile per thread
    auto load_stage = [&](int stage, int kt) {
        int kbase = k0 + kt * TKC;
        uint32_t sbase = smem_u32 + (uint32_t)stage * STAGE_H * 2;
        #pragma unroll
        for (int it = 0; it < 2; it++) {
            int c = tid + it * 512;        // 0..1023
            int row = c >> 3;              // 0..127
            int c16 = c & 7;               // 16B chunk (8 halves)
            uint32_t so = (uint32_t)(row * ROWH + c16 * 8) * 2;
            size_t ao = (size_t)(m0 + row) * lda + kbase + c16 * 8;
            cp16(sbase + A_HI_H*2 + so, Ahi + ao, 16);
            cp16(sbase + A_LO_H*2 + so, Alo + ao, 16);
            int brow = n0 + row;
            int bytes = (brow < Brows) ? 16 : 0;
            int rcl = (brow < Brows) ? brow : (Brows - 1);
            size_t bo = (size_t)rcl * ldb + kbase + c16 * 8;
            cp16(sbase + B_HI_H*2 + so, Bhi + bo, bytes);
            cp16(sbase + B_LO_H*2 + so, Blo + bo, bytes);
        }
    };

    load_stage(0, 0); CP_COMMIT();
    load_stage(1, 1); CP_COMMIT();

    int rowA = lane & 15;
    int colA = (lane >> 4) * 8;
    int r8  = lane & 7;
    int grp = lane >> 3;
    int rowB = ((grp & 1) << 3) + r8;
    int colB = (grp >> 1) * 8;

    for (int kt = 0; kt < nIter; kt++) {
        CP_WAIT(1);
        __syncthreads();
        if (kt + 2 < nIter) { load_stage((kt + 2) % NSTAGES, kt + 2); CP_COMMIT(); }

        uint32_t sbase = smem_u32 + (uint32_t)(kt % NSTAGES) * STAGE_H * 2;
        #pragma unroll
        for (int kk = 0; kk < TKC; kk += 16) {
            uint32_t ah[2][4], al[2][4], bh[4][2], bl[4][2];
            #pragma unroll
            for (int mi = 0; mi < 2; mi++) {
                uint32_t off = (uint32_t)((wm + mi*16 + rowA) * ROWH + kk + colA) * 2;
                ldsm4(ah[mi], sbase + A_HI_H*2 + off);
                ldsm4(al[mi], sbase + A_LO_H*2 + off);
            }
            #pragma unroll
            for (int nh = 0; nh < 2; nh++) {
                uint32_t off = (uint32_t)((wn + nh*16 + rowB) * ROWH + kk + colB) * 2;
                uint32_t t[4];
                ldsm4(t, sbase + B_HI_H*2 + off);
                bh[nh*2][0] = t[0]; bh[nh*2][1] = t[2];
                bh[nh*2+1][0] = t[1]; bh[nh*2+1][1] = t[3];
                ldsm4(t, sbase + B_LO_H*2 + off);
                bl[nh*2][0] = t[0]; bl[nh*2][1] = t[2];
                bl[nh*2+1][0] = t[1]; bl[nh*2+1][1] = t[3];
            }
            // hi*hi into acc_h (8 independent MMAs), corrections into acc_l (chains of 2)
            #pragma unroll
            for (int mi = 0; mi < 2; mi++)
                #pragma unroll
                for (int ni = 0; ni < 4; ni++)
                    mma_bf16(acc_h[mi][ni], ah[mi], bh[ni]);
            #pragma unroll
            for (int mi = 0; mi < 2; mi++)
                #pragma unroll
                for (int ni = 0; ni < 4; ni++) {
                    mma_bf16(acc_l[mi][ni], ah[mi], bl[ni]);
                    mma_bf16(acc_l[mi][ni], al[mi], bh[ni]);
                }
        }
        __syncthreads();
    }

    // -------- epilogue: merge acc_h + acc_l, float2 stores --------
    #pragma unroll
    for (int mi = 0; mi < 2; mi++) {
        int r0 = m0 + wm + mi*16 + (lane >> 2);
        #pragma unroll
        for (int ni = 0; ni < 4; ni++) {
            int c0 = n0 + wn + ni*8 + (lane & 3)*2;
            if (c0 < Ncols) {
                float2 b2v = colBias ? *reinterpret_cast<const float2*>(colBias + c0)
                                     : make_float2(0.0f, 0.0f);
                float2 v0 = make_float2(acc_h[mi][ni][0] + acc_l[mi][ni][0] + b2v.x,
                                        acc_h[mi][ni][1] + acc_l[mi][ni][1] + b2v.y);
                float2 v1 = make_float2(acc_h[mi][ni][2] + acc_l[mi][ni][2] + b2v.x,
                                        acc_h[mi][ni][3] + acc_l[mi][ni][3] + b2v.y);
                if (applyLeaky) {
                    v0.x = (v0.x >= 0.0f) ? v0.x : 0.01f * v0.x;
                    v0.y = (v0.y >= 0.0f) ? v0.y : 0.01f * v0.y;
                    v1.x = (v1.x >= 0.0f) ? v1.x : 0.01f * v1.x;
                    v1.y = (v1.y >= 0.0f) ? v1.y : 0.01f * v1.y;
                }
                *reinterpret_cast<float2*>(C + (size_t)r0 * ldc + c0) = v0;
                *reinterpret_cast<float2*>(C + (size_t)(r0 + 8) * ldc + c0) = v1;
            }
        }
    }
}

// ---------------- splitK combine + bias + leaky -> h1 (fp32), x4 ----------------
__global__ void combine_kernel(const float* __restrict__ b1)
{
    int i4 = blockIdx.x * blockDim.x + threadIdx.x;
    if (i4 >= MROWS * D1 / 4) return;
    int idx = i4 * 4;
    const int MN = MROWS * D1;
    float4 a0 = *reinterpret_cast<const float4*>(g_hp + idx);
    float4 a1 = *reinterpret_cast<const float4*>(g_hp + MN + idx);
    float4 a2 = *reinterpret_cast<const float4*>(g_hp + 2*MN + idx);
    float4 a3 = *reinterpret_cast<const float4*>(g_hp + 3*MN + idx);
    float4 bb = *reinterpret_cast<const float4*>(b1 + (idx % D1));
    float4 v;
    v.x = a0.x + a1.x + a2.x + a3.x + bb.x;
    v.y = a0.y + a1.y + a2.y + a3.y + bb.y;
    v.z = a0.z + a1.z + a2.z + a3.z + bb.z;
    v.w = a0.w + a1.w + a2.w + a3.w + bb.w;
    v.x = (v.x >= 0.0f) ? v.x : 0.01f * v.x;
    v.y = (v.y >= 0.0f) ? v.y : 0.01f * v.y;
    v.z = (v.z >= 0.0f) ? v.z : 0.01f * v.z;
    v.w = (v.w >= 0.0f) ? v.w : 0.01f * v.w;
    *reinterpret_cast<float4*>(g_h1 + idx) = v;
}

// ---------------- BN stats stage 1: grid (3, 64), 2 rows per block ----------------
__global__ void stats_part_kernel(const float* __restrict__ H, int Ncols)
{
    int c = blockIdx.x, chunk = blockIdx.y;
    float s = 0.0f, sq = 0.0f;
    int nc4 = Ncols >> 2;
    for (int r = chunk * 2; r < chunk * 2 + 2; r++) {
        const float* row = H + (size_t)(r * 3 + c) * Ncols;
        const float4* row4 = reinterpret_cast<const float4*>(row);
        for (int col = threadIdx.x; col < nc4; col += blockDim.x) {
            float4 v = row4[col];
            s  += v.x + v.y + v.z + v.w;
            sq += v.x*v.x + v.y*v.y + v.z*v.z + v.w*v.w;
        }
        for (int col = (nc4 << 2) + threadIdx.x; col < Ncols; col += blockDim.x) {
            float v = row[col];
            s += v; sq += v * v;
        }
    }
    #pragma unroll
    for (int o = 16; o; o >>= 1) {
        s  += __shfl_xor_sync(0xffffffffu, s,  o);
        sq += __shfl_xor_sync(0xffffffffu, sq, o);
    }
    __shared__ float sh0[8], sh1[8];
    int lane = threadIdx.x & 31, wid = threadIdx.x >> 5;
    if (lane == 0) { sh0[wid] = s; sh1[wid] = sq; }
    __syncthreads();
    if (threadIdx.x < 32) {
        int nw = blockDim.x >> 5;
        s  = (lane < nw) ? sh0[lane] : 0.0f;
        sq = (lane < nw) ? sh1[lane] : 0.0f;
        #pragma unroll
        for (int o = 16; o; o >>= 1) {
            s  += __shfl_xor_sync(0xffffffffu, s,  o);
            sq += __shfl_xor_sync(0xffffffffu, sq, o);
        }
        if (lane == 0) {
            g_part[(c * 64 + chunk) * 2 + 0] = s;
            g_part[(c * 64 + chunk) * 2 + 1] = sq;
        }
    }
}

__global__ void stats_fin_kernel(int Ncols,
                                 const float* __restrict__ gamma,
                                 const float* __restrict__ beta,
                                 float* __restrict__ aff)
{
    int c = threadIdx.x;
    if (c >= 3) return;
    float s = 0.0f, sq = 0.0f;
    for (int i = 0; i < 64; i++) {
        s  += g_part[(c * 64 + i) * 2 + 0];
        sq += g_part[(c * 64 + i) * 2 + 1];
    }
    float cnt  = (float)NB * (float)Ncols;
    float mean = s / cnt;
    float var  = sq / cnt - mean * mean;
    float a = gamma[c] * rsqrtf(var + 1e-5f);
    aff[c]     = a;
    aff[3 + c] = beta[c] - mean * a;
}

// ---------------- final elementwise BN2 affine -> output, x4 ----------------
__global__ void final_kernel(float* __restrict__ out)
{
    int i4 = blockIdx.x * blockDim.x + threadIdx.x;
    if (i4 >= MROWS * D2 / 4) return;
    int idx = i4 * 4;
    int c = (idx / D2) % 3;
    float a = g_aff2[c], b = g_aff2[3 + c];
    float4 v = *reinterpret_cast<const float4*>(g_h2 + idx);
    v.x = v.x * a + b; v.y = v.y * a + b; v.z = v.z * a + b; v.w = v.w * a + b;
    *reinterpret_cast<float4*>(out + idx) = v;
}

// ---------------- launch ----------------
extern "C" void kernel_launch(void* const* d_in, const int* in_sizes, int n_in,
                              void* d_out, int out_size)
{
    const float* x      = (const float*)d_in[0];
    const int*   coords = (const int*)  d_in[1];
    const float* mask   = (const float*)d_in[2];
    const float* W1     = (const float*)d_in[3];
    const float* b1     = (const float*)d_in[4];
    const float* g1     = (const float*)d_in[5];
    const float* be1    = (const float*)d_in[6];
    const float* W2     = (const float*)d_in[7];
    const float* b2     = (const float*)d_in[8];
    const float* g2     = (const float*)d_in[9];
    const float* be2    = (const float*)d_in[10];
    float* out = (float*)d_out;

    static bool inited = false;
    static __nv_bfloat16 *p_shi, *p_slo, *p_w1hi, *p_w1lo, *p_w2hi, *p_w2lo, *p_h1hi, *p_h1lo;
    static float *p_hp, *p_h1, *p_h2, *p_a1, *p_a2;
    if (!inited) {
        cudaGetSymbolAddress((void**)&p_shi,  g_shi);
        cudaGetSymbolAddress((void**)&p_slo,  g_slo);
        cudaGetSymbolAddress((void**)&p_w1hi, g_w1hi);
        cudaGetSymbolAddress((void**)&p_w1lo, g_w1lo);
        cudaGetSymbolAddress((void**)&p_w2hi, g_w2hi);
        cudaGetSymbolAddress((void**)&p_w2lo, g_w2lo);
        cudaGetSymbolAddress((void**)&p_h1hi, g_h1hi);
        cudaGetSymbolAddress((void**)&p_h1lo, g_h1lo);
        cudaGetSymbolAddress((void**)&p_hp,   g_hp);
        cudaGetSymbolAddress((void**)&p_h1,   g_h1);
        cudaGetSymbolAddress((void**)&p_h2,   g_h2);
        cudaGetSymbolAddress((void**)&p_a1,   g_aff1);
        cudaGetSymbolAddress((void**)&p_a2,   g_aff2);
        cudaFuncSetAttribute(gemm_bf16x3, cudaFuncAttributeMaxDynamicSharedMemorySize, SMEM_BYTES);
        inited = true;
    }

    // 1) gather + mask + split -> s hi/lo
    gather_kernel<<<(MROWS*LL + 255) / 256, 256>>>(x, coords, mask);

    // 2) W1, W2 -> bf16 hi/lo (vectorized x4)
    {
        long t1 = (long)D1 * LL / 4;
        convert_split_kernel<<<(unsigned)((t1 + 255) / 256), 256>>>(W1, LL, LL, p_w1hi, p_w1lo, t1);
        long t2 = (long)D2 * K2P / 4;
        convert_split_kernel<<<(unsigned)((t2 + 255) / 256), 256>>>(W2, D1, K2P, p_w2hi, p_w2lo, t2);
    }

    // 3) GEMM1 split-K: hp[z] = s * W1^T (K slice)
    {
        dim3 grid((D1 + TN - 1) / TN, MROWS / TM, SPLITK);   // (10, 3, 4)
        gemm_bf16x3<<<grid, 512, SMEM_BYTES>>>(
            p_shi, p_slo, LL,
            p_w1hi, p_w1lo, LL, D1,
            p_hp, D1, D1,
            K1CHUNK, (size_t)MROWS * D1,
            nullptr, 0);
    }

    // 4) combine + b1 + leaky -> h1 (fp32)
    combine_kernel<<<(MROWS*D1/4 + 255) / 256, 256>>>(b1);

    // 5) BN1 stats -> affine1; fold into bf16 conversion of h1
    stats_part_kernel<<<dim3(3, 64), 256>>>(p_h1, D1);
    stats_fin_kernel<<<1, 32>>>(D1, g1, be1, p_a1);
    convert_h1_kernel<<<(MROWS*K2P/4 + 255) / 256, 256>>>();

    // 6) GEMM2: h2 = leaky(h1n * W2^T + b2)
    {
        dim3 grid((D2 + TN - 1) / TN, MROWS / TM, 1);        // (38, 3, 1)
        gemm_bf16x3<<<grid, 512, SMEM_BYTES>>>(
            p_h1hi, p_h1lo, K2P,
            p_w2hi, p_w2lo, K2P, D2,
            p_h2, D2, D2,
            K2P, 0,
            b2, 1);
    }

    // 7) BN2 stats -> affine2
    stats_part_kernel<<<dim3(3, 64), 256>>>(p_h2, D2);
    stats_fin_kernel<<<1, 32>>>(D2, g2, be2, p_a2);

    // 8) final affine -> out
    final_kernel<<<(MROWS*D2/4 + 255) / 256, 256>>>(out);
}